// round 12
// baseline (speedup 1.0000x reference)
#include <cuda_runtime.h>
#include <math.h>

#define NB    128
#define NTH   256
#define BB    64
#define TT    512
#define IND   512
#define XD    1024
#define OUTD  256
#define STR   68
#define SMEM_FLOATS 25600            // loop: 8192(As)+2*8704(Bs) ; pre: 8704+8704
#define SMEM_BYTES  (SMEM_FLOATS * 4)

// ------------------------- device scratch ---------------------------------
__device__ float g_actin[(size_t)BB * TT * XD];   // [t*64+b][XD]
__device__ float g_P[(size_t)BB * TT * XD];       // [t*64+b][XD] (bh1 folded)
__device__ float g_h3all[(size_t)TT * BB * XD];   // [t][b][XD]
__device__ float g_hbuf[8][4][8][XD];             // [group][phase][row][col]
__device__ float g_np[8][16][8];                  // [group][local][row] partial ssq
__device__ unsigned g_cnt[8 * 4 * 32];            // [group][phase] monotonic, 128B apart
__device__ unsigned g_barcnt;
__device__ unsigned g_bargen;

// ------------------------- scoped atomics ----------------------------------
__device__ __forceinline__ void red_release_add(unsigned* p) {
    asm volatile("red.release.gpu.add.u32 [%0], %1;" :: "l"(p), "r"(1u) : "memory");
}
__device__ __forceinline__ unsigned ld_acquire(const unsigned* p) {
    unsigned v;
    asm volatile("ld.acquire.gpu.u32 %0, [%1];" : "=r"(v) : "l"(p) : "memory");
    return v;
}

// ------------------------- branch-free fast activation ---------------------
__device__ __forceinline__ float rand_act(float v, int idx, float mx) {
    float en  = __expf(-v);
    float sig = __fdividef(1.0f, 1.0f + en);
    float th  = __fdividef(2.0f, 1.0f + en * en) - 1.0f;
    float sel = (v > 0.0f) ? 1.0507009873554805f * v
                           : 1.7580993408473766f * (__expf(v) - 1.0f);
    float r = (idx == 0) ? fmaxf(v, 0.0f)
            : (idx == 1) ? sig
            : (idx == 2) ? th
            : (idx == 3) ? ((v >= 0.0f) ? v : 0.1f * v)
            : sel;
    return fminf(r, mx);
}

__device__ __forceinline__ float4 act4(float4 v, int4 id, float4 mx) {
    return make_float4(rand_act(v.x, id.x, mx.x), rand_act(v.y, id.y, mx.y),
                       rand_act(v.z, id.z, mx.z), rand_act(v.w, id.w, mx.w));
}

// ------------------------- grid-wide barrier (pre/post loop only) ----------
__device__ __forceinline__ void gsync(unsigned& mygen) {
    __threadfence();
    __syncthreads();
    if (threadIdx.x == 0) {
        unsigned old = atomicAdd(&g_barcnt, 1u);
        if (old == NB - 1u) {
            g_barcnt = 0u;
            __threadfence();
            atomicAdd(&g_bargen, 1u);
        } else {
            while (((volatile unsigned*)&g_bargen)[0] == mygen) { __nanosleep(64); }
        }
    }
    __syncthreads();
    mygen += 1u;
}

// ------------------------- precompute tile helpers (256 thr, proven R10) ---
__device__ __forceinline__ void stage_g(const float* A, int lda, float* Ss) {
    const int r = threadIdx.x & 63, q = threadIdx.x >> 6;
#pragma unroll
    for (int j = 0; j < 8; j++) {
        float4 v = *(const float4*)(A + (size_t)r * lda + 32 * q + 4 * j);
        const int k = 32 * q + 4 * j;
        Ss[(k + 0) * STR + r] = v.x; Ss[(k + 1) * STR + r] = v.y;
        Ss[(k + 2) * STR + r] = v.z; Ss[(k + 3) * STR + r] = v.w;
    }
}

__device__ __forceinline__ void stage_w(const float* W, int ldw, float* Ss) {
    const int r = threadIdx.x & 63, q = threadIdx.x >> 6;
#pragma unroll
    for (int j = 0; j < 8; j++) {
        float4 v = __ldg((const float4*)(W + (size_t)r * ldw + 32 * q + 4 * j));
        const int k = 32 * q + 4 * j;
        Ss[(k + 0) * STR + r] = v.x; Ss[(k + 1) * STR + r] = v.y;
        Ss[(k + 2) * STR + r] = v.z; Ss[(k + 3) * STR + r] = v.w;
    }
}

__device__ __forceinline__ void gemm128(const float* As, const float* Bs,
                                        float acc[4][4]) {
    const int rb = (threadIdx.x >> 4) << 2;
    const int cb = (threadIdx.x & 15) << 2;
#pragma unroll 4
    for (int k = 0; k < 128; k++) {
        float4 a = *(const float4*)(As + k * STR + rb);
        float4 b = *(const float4*)(Bs + k * STR + cb);
        acc[0][0] += a.x * b.x; acc[0][1] += a.x * b.y; acc[0][2] += a.x * b.z; acc[0][3] += a.x * b.w;
        acc[1][0] += a.y * b.x; acc[1][1] += a.y * b.y; acc[1][2] += a.y * b.z; acc[1][3] += a.y * b.w;
        acc[2][0] += a.z * b.x; acc[2][1] += a.z * b.y; acc[2][2] += a.z * b.z; acc[2][3] += a.z * b.w;
        acc[3][0] += a.w * b.x; acc[3][1] += a.w * b.y; acc[3][2] += a.w * b.z; acc[3][3] += a.w * b.w;
    }
}

// ------------------------- main persistent kernel --------------------------
__global__ void __launch_bounds__(NTH, 1)
bnn_kernel(const float* __restrict__ x,
           const float* __restrict__ Wi,  const float* __restrict__ bi,
           const float* __restrict__ Wh1, const float* __restrict__ bh1,
           const float* __restrict__ Wh2, const float* __restrict__ bh2,
           const float* __restrict__ Wh3, const float* __restrict__ bh3,
           const float* __restrict__ Wo,  const float* __restrict__ bo,
           const float* __restrict__ Wr,  const float* __restrict__ br,
           const float* __restrict__ max_in,  const float* __restrict__ max_h1,
           const float* __restrict__ max_h2,  const float* __restrict__ max_h3,
           const float* __restrict__ max_out, const float* __restrict__ max_rec,
           const int* __restrict__ idx_in,  const int* __restrict__ idx_h1,
           const int* __restrict__ idx_h2,  const int* __restrict__ idx_h3,
           const int* __restrict__ idx_out, const int* __restrict__ idx_rec,
           float* __restrict__ out) {
    extern __shared__ float sm[];
    const int bid = blockIdx.x;
    const int tid = threadIdx.x;

    unsigned mygen = ((volatile unsigned*)&g_bargen)[0];

    // ---- init (every launch; graph replays reuse state) ----
    {
        float* hb = &g_hbuf[0][0][0][0];
        for (int i = bid * NTH + tid; i < 8 * 4 * 8 * XD; i += NB * NTH) hb[i] = 0.0f;
        if (bid == 0) {
            for (int j = tid; j < 8 * 16 * 8; j += NTH) ((float*)g_np)[j] = 0.0f;
            for (int j = tid; j < 8 * 4 * 32; j += NTH) g_cnt[j] = 0u;
        }
    }
    gsync(mygen);

    // ================= Phase A: actin = act(x @ Wi^T + bi), permuted =======
    {
        float* pAs = sm; float* pBs = sm + 8704;
        for (int task = bid; task < 512 * 16; task += NB) {
            const int rt = task >> 4, nt2 = task & 15;
            float acc[4][4] = {};
            for (int c = 0; c < 4; c++) {
                stage_g(x + (size_t)rt * 64 * IND + c * 128, IND, pAs);
                stage_w(Wi + (size_t)(nt2 << 6) * IND + c * 128, IND, pBs);
                __syncthreads();
                gemm128(pAs, pBs, acc);
                __syncthreads();
            }
            const int rb = (tid >> 4) << 2;
            const int col0 = (nt2 << 6) + ((tid & 15) << 2);
            const int4   id4 = __ldg((const int4*)&idx_in[col0]);
            const float4 mx4 = __ldg((const float4*)&max_in[col0]);
            const float4 b4  = __ldg((const float4*)&bi[col0]);
#pragma unroll
            for (int i = 0; i < 4; i++) {
                const int gg = rt * 64 + rb + i;
                const int b = gg >> 9, t = gg & 511;
                float4 v = make_float4(acc[i][0] + b4.x, acc[i][1] + b4.y,
                                       acc[i][2] + b4.z, acc[i][3] + b4.w);
                v = act4(v, id4, mx4);
                *(float4*)&g_actin[(size_t)(t * BB + b) * XD + col0] = v;
            }
        }
    }
    gsync(mygen);

    // ================= Phase B: P = actin @ Wh1a^T + bh1 ===================
    {
        float* pAs = sm; float* pBs = sm + 8704;
        for (int task = bid; task < 512 * 16; task += NB) {
            const int rt = task >> 4, nt2 = task & 15;
            float acc[4][4] = {};
            for (int c = 0; c < 8; c++) {
                stage_g(g_actin + (size_t)rt * 64 * XD + c * 128, XD, pAs);
                stage_w(Wh1 + (size_t)(nt2 << 6) * (2 * XD) + c * 128, 2 * XD, pBs);
                __syncthreads();
                gemm128(pAs, pBs, acc);
                __syncthreads();
            }
            const int rb = (tid >> 4) << 2;
            const int col0 = (nt2 << 6) + ((tid & 15) << 2);
            const float4 b4 = __ldg((const float4*)&bh1[col0]);
#pragma unroll
            for (int i = 0; i < 4; i++) {
                const int row = rt * 64 + rb + i;
                float4 v = make_float4(acc[i][0] + b4.x, acc[i][1] + b4.y,
                                       acc[i][2] + b4.z, acc[i][3] + b4.w);
                *(float4*)&g_P[(size_t)row * XD + col0] = v;
            }
        }
    }
    gsync(mygen);

    // ================= time loop: 8 INDEPENDENT row-groups ==================
    {
        const int g     = bid >> 4;          // group 0..7 (rows 8g..8g+7)
        const int local = bid & 15;          // col slice 0..15
        const int n0    = local << 6;
        const int cc    = tid & 63;          // col within slice
        const int rp    = tid >> 6;          // row pair 0..3
        unsigned* cnts  = g_cnt + g * 4 * 32;
        float* As  = sm;                     // 8x1024 input copy
        float* Bs  = sm + 8192;              // weight chunk (single buffer)

        const float* wbase0 = Wh1 + XD + (size_t)(n0 + cc) * (2 * XD);  // ph0 row base
        for (int s = 0; s < TT; s++) {
#pragma unroll 1
            for (int ph = 0; ph < 4; ph++) {
                const int prev = (ph + 3) & 3;
                const unsigned tgt = (ph == 0) ? 16u * (unsigned)s : 16u * (unsigned)(s + 1);
                if (tid == 0) { while (ld_acquire(&cnts[prev * 32]) < tgt) {} }
                __syncthreads();

                // rinv for ph0 (rows 2rp, 2rp+1)
                float rinv0 = 0.f, rinv1 = 0.f;
                if (ph == 0) {
                    float s0 = 0.f, s1 = 0.f;
#pragma unroll
                    for (int l = 0; l < 16; l++) {
                        s0 += __ldcg(&g_np[g][l][2 * rp]);
                        s1 += __ldcg(&g_np[g][l][2 * rp + 1]);
                    }
                    rinv0 = __fdividef(1.0f, fmaxf(__fsqrt_rn(s0), 1e-12f));
                    rinv1 = __fdividef(1.0f, fmaxf(__fsqrt_rn(s1), 1e-12f));
                }

                // stage A: flat copy of 8x1024 input (final values from prev phase)
                {
                    const float4* src = (const float4*)&g_hbuf[g][prev][0][0];
                    float4* dst = (float4*)As;
#pragma unroll
                    for (int j = 0; j < 8; j++) dst[tid * 8 + j] = __ldcg(&src[tid * 8 + j]);
                }

                // weight row base for this thread's column (wr == cc)
                const float* wrow =
                    (ph == 0) ? wbase0 :
                    (ph == 1) ? Wh2 + (size_t)(n0 + cc) * XD :
                    (ph == 2) ? Wh3 + (size_t)(n0 + cc) * XD :
                                Wr  + (size_t)(n0 + cc) * XD;
                const float* wld = ((ph == 0) ? Wh1 + XD + (size_t)(n0 + (tid & 63)) * (2 * XD)
                                              : wrow) + (tid >> 6) * 32;
                // NOTE: staging thread mapping == (wr = tid&63, wq = tid>>6); since
                // wr == cc this reuses wrow for ph>0 and the explicit base for ph0.

                float4 wv[8];
#pragma unroll
                for (int j = 0; j < 8; j++) wv[j] = __ldg((const float4*)(wld + 4 * j));

                __syncthreads();   // As ready; Bs free (prior compute done)

                float acc0 = 0.f, acc1 = 0.f;
                const float* arow0 = As + (2 * rp) * XD;
                const float* arow1 = arow0 + XD;
#pragma unroll 1
                for (int ch = 0; ch < 8; ch++) {
                    const int wr = tid & 63, wq = tid >> 6;
#pragma unroll
                    for (int j = 0; j < 8; j++) {
                        const int k = wq * 32 + 4 * j;
                        Bs[(k + 0) * STR + wr] = wv[j].x;
                        Bs[(k + 1) * STR + wr] = wv[j].y;
                        Bs[(k + 2) * STR + wr] = wv[j].z;
                        Bs[(k + 3) * STR + wr] = wv[j].w;
                    }
                    __syncthreads();
                    if (ch < 7) {
                        const float* wb2 = wld + (ch + 1) * 128;
#pragma unroll
                        for (int j = 0; j < 8; j++) wv[j] = __ldg((const float4*)(wb2 + 4 * j));
                    }
                    const float* a0p = arow0 + ch * 128;
                    const float* a1p = arow1 + ch * 128;
#pragma unroll 8
                    for (int kk = 0; kk < 128; kk += 4) {
                        float4 a0 = *(const float4*)(a0p + kk);
                        float4 a1 = *(const float4*)(a1p + kk);
                        float b0 = Bs[(kk + 0) * STR + cc];
                        float b1 = Bs[(kk + 1) * STR + cc];
                        float b2 = Bs[(kk + 2) * STR + cc];
                        float b3 = Bs[(kk + 3) * STR + cc];
                        acc0 += a0.x * b0; acc1 += a1.x * b0;
                        acc0 += a0.y * b1; acc1 += a1.y * b1;
                        acc0 += a0.z * b2; acc1 += a1.z * b2;
                        acc0 += a0.w * b3; acc1 += a1.w * b3;
                    }
                    __syncthreads();
                }

                // ---- epilogue: bias/act, store final h slice ----
                const int gc = n0 + cc;
                const int growbase = g * 8 + 2 * rp;
                float v0, v1;
                if (ph == 0) {
                    const float* Prow = g_P + ((size_t)s * BB + growbase) * XD + gc;
                    const int   id1 = __ldg(&idx_h1[gc]);
                    const float mx1 = __ldg(&max_h1[gc]);
                    v0 = rand_act(acc0 * rinv0 + __ldcg(Prow),      id1, mx1);
                    v1 = rand_act(acc1 * rinv1 + __ldcg(Prow + XD), id1, mx1);
                } else {
                    const float* bias = (ph == 1) ? bh2 : (ph == 2) ? bh3 : br;
                    const int*   idx  = (ph == 1) ? idx_h2 : (ph == 2) ? idx_h3 : idx_rec;
                    const float* mxa  = (ph == 1) ? max_h2 : (ph == 2) ? max_h3 : max_rec;
                    const int   id1 = __ldg(&idx[gc]);
                    const float mx1 = __ldg(&mxa[gc]);
                    const float b   = __ldg(&bias[gc]);
                    v0 = rand_act(acc0 + b, id1, mx1);
                    v1 = rand_act(acc1 + b, id1, mx1);
                }
                __stcg(&g_hbuf[g][ph][2 * rp][gc],     v0);
                __stcg(&g_hbuf[g][ph][2 * rp + 1][gc], v1);
                if (ph == 2) {
                    __stcg(&g_h3all[((size_t)s * BB + growbase) * XD + gc],     v0);
                    __stcg(&g_h3all[((size_t)s * BB + growbase + 1) * XD + gc], v1);
                }
                if (ph == 3) {
                    float sq0 = v0 * v0, sq1 = v1 * v1;
#pragma unroll
                    for (int o = 16; o; o >>= 1) {
                        sq0 += __shfl_xor_sync(0xffffffffu, sq0, o);
                        sq1 += __shfl_xor_sync(0xffffffffu, sq1, o);
                    }
                    const int wid = tid >> 5;   // warp: rp = wid>>1, col-half = wid&1
                    if ((tid & 31) == 0) { As[wid * 2 + 0] = sq0; As[wid * 2 + 1] = sq1; }
                    __syncthreads();
                    if (tid < 8) {
                        const int rpp = tid >> 1, rb2 = tid & 1;
                        float v = As[(rpp * 2 + 0) * 2 + rb2] + As[(rpp * 2 + 1) * 2 + rb2];
                        __stcg(&g_np[g][local][2 * rpp + rb2], v);
                    }
                }
                __syncthreads();
                if (tid == 0) red_release_add(&cnts[ph * 32]);
            }
        }
    }
    gsync(mygen);

    // ================= Output GEMM: y = act(H3 @ Wo^T + bo) ================
    {
        float* pAs = sm; float* pBs = sm + 8704;
        for (int task = bid; task < 512 * 4; task += NB) {
            const int t = task >> 2, ot = task & 3;
            float acc[4][4] = {};
            for (int c = 0; c < 8; c++) {
                stage_g(g_h3all + (size_t)t * BB * XD + c * 128, XD, pAs);
                stage_w(Wo + (size_t)(ot << 6) * XD + c * 128, XD, pBs);
                __syncthreads();
                gemm128(pAs, pBs, acc);
                __syncthreads();
            }
            const int rb = (tid >> 4) << 2;
            const int oc0 = (ot << 6) + ((tid & 15) << 2);
            const int4   id4 = __ldg((const int4*)&idx_out[oc0]);
            const float4 mx4 = __ldg((const float4*)&max_out[oc0]);
            const float4 b4  = __ldg((const float4*)&bo[oc0]);
#pragma unroll
            for (int i = 0; i < 4; i++) {
                const int b = rb + i;
                float4 v = make_float4(acc[i][0] + b4.x, acc[i][1] + b4.y,
                                       acc[i][2] + b4.z, acc[i][3] + b4.w);
                v = act4(v, id4, mx4);
                *(float4*)&out[((size_t)b * TT + t) * OUTD + oc0] = v;
            }
        }
    }
}

// ------------------------- launch ------------------------------------------
extern "C" void kernel_launch(void* const* d_in, const int* in_sizes, int n_in,
                              void* d_out, int out_size) {
    const float* x       = (const float*)d_in[0];
    const float* Wi      = (const float*)d_in[1];
    const float* bi      = (const float*)d_in[2];
    const float* Wh1     = (const float*)d_in[3];
    const float* bh1     = (const float*)d_in[4];
    const float* Wh2     = (const float*)d_in[5];
    const float* bh2     = (const float*)d_in[6];
    const float* Wh3     = (const float*)d_in[7];
    const float* bh3     = (const float*)d_in[8];
    const float* Wo      = (const float*)d_in[9];
    const float* bo      = (const float*)d_in[10];
    const float* Wr      = (const float*)d_in[11];
    const float* br      = (const float*)d_in[12];
    const float* max_in  = (const float*)d_in[13];
    const float* max_h1  = (const float*)d_in[14];
    const float* max_h2  = (const float*)d_in[15];
    const float* max_h3  = (const float*)d_in[16];
    const float* max_out = (const float*)d_in[17];
    const float* max_rec = (const float*)d_in[18];
    const int*   idx_in  = (const int*)d_in[19];
    const int*   idx_h1  = (const int*)d_in[20];
    const int*   idx_h2  = (const int*)d_in[21];
    const int*   idx_h3  = (const int*)d_in[22];
    const int*   idx_out = (const int*)d_in[23];
    const int*   idx_rec = (const int*)d_in[24];

    static int configured = 0;
    if (!configured) {
        cudaFuncSetAttribute(bnn_kernel, cudaFuncAttributeMaxDynamicSharedMemorySize,
                             SMEM_BYTES);
        configured = 1;
    }

    bnn_kernel<<<NB, NTH, SMEM_BYTES>>>(x, Wi, bi, Wh1, bh1, Wh2, bh2, Wh3, bh3,
                                        Wo, bo, Wr, br,
                                        max_in, max_h1, max_h2, max_h3, max_out, max_rec,
                                        idx_in, idx_h1, idx_h2, idx_h3, idx_out, idx_rec,
                                        (float*)d_out);
}

// round 16
// speedup vs baseline: 3.6277x; 3.6277x over previous
#include <cuda_runtime.h>
#include <cuda_bf16.h>
#include <stdint.h>
#include <math.h>

#define NB    128
#define NTH   512
#define BB    64
#define TT    512
#define IND   512
#define XD    1024
#define OUTD  256

// precompute scratch strides (R6, proven)
#define P_ASTR 132
#define P_BSTR 68

// loop-mode SMEM byte map: bf16 tiles, 64 rows x 128 cols, row stride 136 halves (272 B)
#define TILE_B   17408               // 64 * 136 * 2 bytes
#define SM_AHI   0
#define SM_ALO   TILE_B
#define SM_W     (2 * TILE_B)        // 8 tiles: ph0..3 x {hi,lo}
#define SMEM_BYTES (10 * TILE_B)     // 174080

typedef unsigned long long ull;

#define FMA2(c, a, b) asm("fma.rn.f32x2 %0, %1, %2, %0;" : "+l"(c) : "l"(a), "l"(b))
#define UNPK(c, lo, hi) asm("mov.b64 {%0, %1}, %2;" : "=f"(lo), "=f"(hi) : "l"(c))

// ------------------------- device scratch ---------------------------------
__device__ float g_actin[(size_t)BB * TT * XD];
__device__ float g_P[(size_t)BB * TT * XD];        // bh1 folded in
__device__ float g_h3all[(size_t)TT * BB * XD];
__device__ float g_h1[BB * XD];
__device__ float g_h2[BB * XD];
__device__ float g_rs[BB * XD];
__device__ float g_normpart[BB][16];
__device__ float g_part[64 * 8 * 4096];
__device__ unsigned g_scnt[64 * 8];
__device__ unsigned g_hcnt[64 * 8];
__device__ unsigned g_barcnt;
__device__ unsigned g_bargen;

// ------------------------- scoped atomics ----------------------------------
__device__ __forceinline__ unsigned atom_acqrel_add(unsigned* p) {
    unsigned o;
    asm volatile("atom.acq_rel.gpu.add.u32 %0, [%1], %2;"
                 : "=r"(o) : "l"(p), "r"(1u) : "memory");
    return o;
}
__device__ __forceinline__ void red_release_add(unsigned* p) {
    asm volatile("red.release.gpu.add.u32 [%0], %1;" :: "l"(p), "r"(1u) : "memory");
}
__device__ __forceinline__ unsigned ld_acquire(const unsigned* p) {
    unsigned v;
    asm volatile("ld.acquire.gpu.u32 %0, [%1];" : "=r"(v) : "l"(p) : "memory");
    return v;
}

// ------------------------- mma.sync / ldmatrix wrappers --------------------
__device__ __forceinline__ uint32_t smem_u32(const void* p) {
    return (uint32_t)__cvta_generic_to_shared(p);
}
__device__ __forceinline__ void ldsm4(unsigned r[4], uint32_t addr) {
    asm volatile("ldmatrix.sync.aligned.m8n8.x4.shared.b16 {%0,%1,%2,%3}, [%4];"
        : "=r"(r[0]), "=r"(r[1]), "=r"(r[2]), "=r"(r[3]) : "r"(addr));
}
__device__ __forceinline__ void hmma(float c[4], const unsigned a[4],
                                     unsigned b0, unsigned b1) {
    asm volatile("mma.sync.aligned.m16n8k16.row.col.f32.bf16.bf16.f32 "
        "{%0,%1,%2,%3}, {%4,%5,%6,%7}, {%8,%9}, {%0,%1,%2,%3};"
        : "+f"(c[0]), "+f"(c[1]), "+f"(c[2]), "+f"(c[3])
        : "r"(a[0]), "r"(a[1]), "r"(a[2]), "r"(a[3]), "r"(b0), "r"(b1));
}

// ------------------------- branch-free fast activation ---------------------
__device__ __forceinline__ float rand_act(float v, int idx, float mx) {
    float en  = __expf(-v);
    float sig = __fdividef(1.0f, 1.0f + en);
    float th  = __fdividef(2.0f, 1.0f + en * en) - 1.0f;
    float sel = (v > 0.0f) ? 1.0507009873554805f * v
                           : 1.7580993408473766f * (__expf(v) - 1.0f);
    float r = (idx == 0) ? fmaxf(v, 0.0f)
            : (idx == 1) ? sig
            : (idx == 2) ? th
            : (idx == 3) ? ((v >= 0.0f) ? v : 0.1f * v)
            : sel;
    return fminf(r, mx);
}
__device__ __forceinline__ float4 act4(float4 v, int4 id, float4 mx) {
    return make_float4(rand_act(v.x, id.x, mx.x), rand_act(v.y, id.y, mx.y),
                       rand_act(v.z, id.z, mx.z), rand_act(v.w, id.w, mx.w));
}

// ------------------------- grid barrier (pre/post loop) --------------------
__device__ __forceinline__ void gsync(unsigned& mygen) {
    __threadfence();
    __syncthreads();
    if (threadIdx.x == 0) {
        unsigned old = atomicAdd(&g_barcnt, 1u);
        if (old == NB - 1u) {
            g_barcnt = 0u;
            __threadfence();
            atomicAdd(&g_bargen, 1u);
        } else {
            while (((volatile unsigned*)&g_bargen)[0] == mygen) { __nanosleep(64); }
        }
    }
    __syncthreads();
    mygen += 1u;
}

__device__ __forceinline__ void waitcnt(const unsigned* c0, const unsigned* c1, unsigned tgt) {
    if (threadIdx.x < 2) {
        const unsigned* p = threadIdx.x ? c1 : c0;
        while (ld_acquire(p) < tgt) {}
    }
    __syncthreads();
}

// ------------------------- precompute helpers (R6, proven) -----------------
__device__ __forceinline__ void stageA_dup(const float* __restrict__ A, int lda, float* As2) {
    const int row = threadIdx.x >> 3;
    const int f4  = threadIdx.x & 7;
    const float4* src = (const float4*)(A + (size_t)row * lda);
#pragma unroll
    for (int j = 0; j < 4; j++) {
        float4 v = __ldcg(&src[f4 + 8 * j]);
        const int k = (f4 + 8 * j) << 2;
        *(float2*)(As2 + (size_t)(k + 0) * P_ASTR + 2 * row) = make_float2(v.x, v.x);
        *(float2*)(As2 + (size_t)(k + 1) * P_ASTR + 2 * row) = make_float2(v.y, v.y);
        *(float2*)(As2 + (size_t)(k + 2) * P_ASTR + 2 * row) = make_float2(v.z, v.z);
        *(float2*)(As2 + (size_t)(k + 3) * P_ASTR + 2 * row) = make_float2(v.w, v.w);
    }
}
__device__ __forceinline__ void stageB_T(const float* __restrict__ B, int ldb, float* Bs) {
    const int row = threadIdx.x >> 3;
    const int f4  = threadIdx.x & 7;
    const float4* src = (const float4*)(B + (size_t)row * ldb);
#pragma unroll
    for (int j = 0; j < 4; j++) {
        float4 v = __ldg(&src[f4 + 8 * j]);
        const int k = (f4 + 8 * j) << 2;
        Bs[(size_t)(k + 0) * P_BSTR + row] = v.x;
        Bs[(size_t)(k + 1) * P_BSTR + row] = v.y;
        Bs[(size_t)(k + 2) * P_BSTR + row] = v.z;
        Bs[(size_t)(k + 3) * P_BSTR + row] = v.w;
    }
}
__device__ __forceinline__ void gemm_sh(const float* As2, const float* Bsh,
                                        ull& c00, ull& c01, ull& c10, ull& c11,
                                        int tx, int ty) {
    const float* ap = As2 + (ty << 2);
    const float* bp = Bsh + (tx << 2);
#pragma unroll 8
    for (int k = 0; k < 128; k++) {
        ulonglong2 a = *(const ulonglong2*)(ap + (size_t)k * P_ASTR);
        ulonglong2 b = *(const ulonglong2*)(bp + (size_t)k * P_BSTR);
        FMA2(c00, a.x, b.x); FMA2(c01, a.x, b.y);
        FMA2(c10, a.y, b.x); FMA2(c11, a.y, b.y);
    }
}
__device__ __forceinline__ void unpack_acc(ull c00, ull c01, ull c10, ull c11,
                                           float acc[2][4]) {
    UNPK(c00, acc[0][0], acc[0][1]); UNPK(c01, acc[0][2], acc[0][3]);
    UNPK(c10, acc[1][0], acc[1][1]); UNPK(c11, acc[1][2], acc[1][3]);
}
__device__ __forceinline__ void gemm_task(const float* A, int lda,
                                          const float* B, int ldb,
                                          int nchunk, float acc[2][4],
                                          float* As2, float* Bs, int tx, int ty) {
    ull c00 = 0, c01 = 0, c10 = 0, c11 = 0;
    for (int c = 0; c < nchunk; c++) {
        stageA_dup(A + (c << 7), lda, As2);
        stageB_T(B + (c << 7), ldb, Bs);
        __syncthreads();
        gemm_sh(As2, Bs, c00, c01, c10, c11, tx, ty);
        __syncthreads();
    }
    unpack_acc(c00, c01, c10, c11, acc);
}

// ------------------------- bf16 hi/lo split staging ------------------------
// 64 rows x 128 cols fp32 (row stride lds) -> hi/lo bf16 tiles [64][136 halves]
template<bool CONST>
__device__ __forceinline__ void stage_split(const float* src, int lds,
                                            char* hi, char* lo) {
    const int row = threadIdx.x >> 3;
    const int cb  = (threadIdx.x & 7) << 4;      // 16 cols per thread
    const float4* s = (const float4*)(src + (size_t)row * lds + cb);
    unsigned hp[8], lp[8];
#pragma unroll
    for (int j = 0; j < 4; j++) {
        float4 v = CONST ? __ldg(s + j) : __ldcg(s + j);
        __nv_bfloat16 hx = __float2bfloat16(v.x), hy = __float2bfloat16(v.y);
        __nv_bfloat16 hz = __float2bfloat16(v.z), hw = __float2bfloat16(v.w);
        __nv_bfloat16 lx = __float2bfloat16(v.x - __bfloat162float(hx));
        __nv_bfloat16 ly = __float2bfloat16(v.y - __bfloat162float(hy));
        __nv_bfloat16 lz = __float2bfloat16(v.z - __bfloat162float(hz));
        __nv_bfloat16 lw = __float2bfloat16(v.w - __bfloat162float(hw));
        __nv_bfloat162 h01 = __halves2bfloat162(hx, hy);
        __nv_bfloat162 h23 = __halves2bfloat162(hz, hw);
        __nv_bfloat162 l01 = __halves2bfloat162(lx, ly);
        __nv_bfloat162 l23 = __halves2bfloat162(lz, lw);
        hp[2 * j]     = *(unsigned*)&h01; hp[2 * j + 1] = *(unsigned*)&h23;
        lp[2 * j]     = *(unsigned*)&l01; lp[2 * j + 1] = *(unsigned*)&l23;
    }
    char* hd = hi + ((size_t)row * 136 + cb) * 2;
    char* ld = lo + ((size_t)row * 136 + cb) * 2;
    ((uint4*)hd)[0] = make_uint4(hp[0], hp[1], hp[2], hp[3]);
    ((uint4*)hd)[1] = make_uint4(hp[4], hp[5], hp[6], hp[7]);
    ((uint4*)ld)[0] = make_uint4(lp[0], lp[1], lp[2], lp[3]);
    ((uint4*)ld)[1] = make_uint4(lp[4], lp[5], lp[6], lp[7]);
}

// ------------------------- main persistent kernel --------------------------
__global__ void __launch_bounds__(NTH, 1)
bnn_kernel(const float* __restrict__ x,
           const float* __restrict__ Wi,  const float* __restrict__ bi,
           const float* __restrict__ Wh1, const float* __restrict__ bh1,
           const float* __restrict__ Wh2, const float* __restrict__ bh2,
           const float* __restrict__ Wh3, const float* __restrict__ bh3,
           const float* __restrict__ Wo,  const float* __restrict__ bo,
           const float* __restrict__ Wr,  const float* __restrict__ br,
           const float* __restrict__ max_in,  const float* __restrict__ max_h1,
           const float* __restrict__ max_h2,  const float* __restrict__ max_h3,
           const float* __restrict__ max_out, const float* __restrict__ max_rec,
           const int* __restrict__ idx_in,  const int* __restrict__ idx_h1,
           const int* __restrict__ idx_h2,  const int* __restrict__ idx_h3,
           const int* __restrict__ idx_out, const int* __restrict__ idx_rec,
           float* __restrict__ out) {
    extern __shared__ char smraw[];
    float* smf = (float*)smraw;

    const int bid = blockIdx.x;
    const int tid = threadIdx.x;
    const int tx  = tid & 15;
    const int ty  = tid >> 4;
    const int lane = tid & 31;
    const int w    = tid >> 5;         // warp 0..15
    const int mw   = w >> 2;           // output row block (16 rows)
    const int nw   = w & 3;            // output col block (16 cols)

    unsigned mygen = ((volatile unsigned*)&g_bargen)[0];

    // ---- init (every launch) ----
    for (int i = bid * NTH + tid; i < BB * XD; i += NB * NTH) g_rs[i] = 0.0f;
    if (bid == 0) {
        for (int j = tid; j < BB * 16; j += NTH) ((float*)g_normpart)[j] = 0.0f;
        if (tid < 64 * 8) { g_scnt[tid] = 0u; g_hcnt[tid] = 0u; }
    }
    gsync(mygen);

    // ================= Phase A: actin (fp32 FFMA2 path, proven) ============
    {
        float* pAs2 = smf; float* pBs = smf + 128 * P_ASTR;
        for (int task = bid; task < 512 * 16; task += NB) {
            const int rt = task >> 4, nt2 = task & 15;
            float acc[2][4];
            gemm_task(x + (size_t)rt * 64 * IND, IND,
                      Wi + (size_t)(nt2 << 6) * IND, IND, 4, acc, pAs2, pBs, tx, ty);
            const int col0 = (nt2 << 6) + (tx << 2);
            const int4   id4 = __ldg((const int4*)&idx_in[col0]);
            const float4 mx4 = __ldg((const float4*)&max_in[col0]);
            const float4 b4  = __ldg((const float4*)&bi[col0]);
#pragma unroll
            for (int i = 0; i < 2; i++) {
                const int g = rt * 64 + (ty << 1) + i;
                const int b = g >> 9, t = g & 511;
                float4 v = make_float4(acc[i][0] + b4.x, acc[i][1] + b4.y,
                                       acc[i][2] + b4.z, acc[i][3] + b4.w);
                v = act4(v, id4, mx4);
                __stcg((float4*)&g_actin[(size_t)(t * BB + b) * XD + col0], v);
            }
        }
    }
    gsync(mygen);

    // ================= Phase B: P = actin @ Wh1a^T + bh1 ===================
    {
        float* pAs2 = smf; float* pBs = smf + 128 * P_ASTR;
        for (int task = bid; task < 512 * 16; task += NB) {
            const int rt = task >> 4, nt2 = task & 15;
            float acc[2][4];
            gemm_task(g_actin + (size_t)rt * 64 * XD, XD,
                      Wh1 + (size_t)(nt2 << 6) * (2 * XD), 2 * XD, 8, acc, pAs2, pBs, tx, ty);
            const int col0 = (nt2 << 6) + (tx << 2);
            const float4 b4 = __ldg((const float4*)&bh1[col0]);
#pragma unroll
            for (int i = 0; i < 2; i++) {
                const int r = rt * 64 + (ty << 1) + i;
                float4 v = make_float4(acc[i][0] + b4.x, acc[i][1] + b4.y,
                                       acc[i][2] + b4.z, acc[i][3] + b4.w);
                __stcg((float4*)&g_P[(size_t)r * XD + col0], v);
            }
        }
    }
    gsync(mygen);

    // ================= loop setup: pre-split weights into SMEM =============
    const int nt = bid >> 3;
    const int sp = bid & 7;
    const int n0 = nt << 6;
    const int k0 = sp << 7;
    const int col0 = n0 + (tx << 2);

    {
        const float* wsrc[4] = { Wh1 + XD + (size_t)n0 * (2 * XD) + k0,
                                 Wh2 + (size_t)n0 * XD + k0,
                                 Wh3 + (size_t)n0 * XD + k0,
                                 Wr  + (size_t)n0 * XD + k0 };
        const int ldw[4] = { 2 * XD, XD, XD, XD };
#pragma unroll 1
        for (int ph = 0; ph < 4; ph++)
            stage_split<true>(wsrc[ph], ldw[ph],
                              smraw + SM_W + ph * (2 * TILE_B),
                              smraw + SM_W + ph * (2 * TILE_B) + TILE_B);
    }
    __syncthreads();

    // ldmatrix per-lane fragment offset within a 16x16 region (bytes)
    const uint32_t fragoff = (uint32_t)(((lane & 15) * 136 + ((lane >> 4) << 3)) * 2);
    const uint32_t aHiB = smem_u32(smraw + SM_AHI) + (uint32_t)(mw * 16 * 272) + fragoff;
    const uint32_t aLoB = smem_u32(smraw + SM_ALO) + (uint32_t)(mw * 16 * 272) + fragoff;

    // ================= time loop ============================================
    for (int s = 0; s < TT; s++) {
        const unsigned e = (unsigned)(s + 1);
#pragma unroll 1
        for (int ph = 0; ph < 4; ph++) {
            // ---- wait for producer tiles ----
            const int pslot = (ph == 0) ? 3 : (ph - 1);
            const unsigned tgt = (ph == 0) ? (unsigned)s : e;
            waitcnt(&g_hcnt[(pslot * 16 + 2 * sp) * 8],
                    &g_hcnt[(pslot * 16 + 2 * sp + 1) * 8], tgt);

            // ---- stage A (bf16 hi/lo split) ----
            const float* Asrc = (ph == 0) ? g_rs + k0 :
                                (ph == 1) ? g_h1 + k0 :
                                (ph == 2) ? g_h2 + k0 :
                                            g_h3all + (size_t)s * BB * XD + k0;
            stage_split<false>(Asrc, XD, smraw + SM_AHI, smraw + SM_ALO);
            __syncthreads();

            // ---- 3-pass bf16 HMMA: 16x16 per warp ----
            // B tiles are [n][k] row-major == K x N col-major: NON-trans ldmatrix
            // with n-row addresses yields the exact mma B fragment.
            const uint32_t bHiB = smem_u32(smraw + SM_W + ph * (2 * TILE_B))
                                + (uint32_t)(nw * 16 * 272) + fragoff;
            const uint32_t bLoB = bHiB + (uint32_t)TILE_B;
            float c0[4] = {0.f, 0.f, 0.f, 0.f};
            float c1[4] = {0.f, 0.f, 0.f, 0.f};
#pragma unroll
            for (int ks = 0; ks < 8; ks++) {
                const uint32_t o = (uint32_t)(ks * 32);
                unsigned ah[4], al[4], bh[4], bl[4];
                ldsm4(ah, aHiB + o);
                ldsm4(al, aLoB + o);
                ldsm4(bh, bHiB + o);
                ldsm4(bl, bLoB + o);
                hmma(c0, ah, bh[0], bh[2]); hmma(c1, ah, bh[1], bh[3]);
                hmma(c0, ah, bl[0], bl[2]); hmma(c1, ah, bl[1], bl[3]);
                hmma(c0, al, bh[0], bh[2]); hmma(c1, al, bh[1], bh[3]);
            }
            __syncthreads();   // A buffer free for next phase's staging

            // ---- store slab (fragment layout) ----
            const int slot = ph * 16 + nt;
            {
                float* slab = g_part + ((size_t)slot * 8 + sp) * 4096;
                const int r0 = mw * 16 + (lane >> 2);
                const int cl = nw * 16 + ((lane & 3) << 1);
                __stcg((float2*)&slab[r0 * 64 + cl],            make_float2(c0[0], c0[1]));
                __stcg((float2*)&slab[(r0 + 8) * 64 + cl],      make_float2(c0[2], c0[3]));
                __stcg((float2*)&slab[r0 * 64 + cl + 8],        make_float2(c1[0], c1[1]));
                __stcg((float2*)&slab[(r0 + 8) * 64 + cl + 8],  make_float2(c1[2], c1[3]));
            }
            __syncthreads();

            // ---- arrival counter; 8th block reduces + epilogue ----
            __shared__ unsigned s_old;
            if (tid == 0) s_old = atom_acqrel_add(&g_scnt[slot * 8]);
            __syncthreads();
            if (s_old == 8u * e - 1u) {
                float acc[2][4];
#pragma unroll
                for (int i = 0; i < 2; i++)
#pragma unroll
                    for (int j = 0; j < 4; j++) acc[i][j] = 0.0f;
#pragma unroll
                for (int sl = 0; sl < 8; sl++) {
                    const float* os = &g_part[((size_t)slot * 8 + sl) * 4096];
#pragma unroll
                    for (int i = 0; i < 2; i++) {
                        float4 pv = __ldcg((const float4*)&os[((ty << 1) + i) * 64 + (tx << 2)]);
                        acc[i][0] += pv.x; acc[i][1] += pv.y;
                        acc[i][2] += pv.z; acc[i][3] += pv.w;
                    }
                }
                if (ph == 0) {
                    const int4   id4 = __ldg((const int4*)&idx_h1[col0]);
                    const float4 mx4 = __ldg((const float4*)&max_h1[col0]);
                    const float* Pt = g_P + (size_t)s * BB * XD;
#pragma unroll
                    for (int i = 0; i < 2; i++) {
                        const int row = (ty << 1) + i;
                        float4 n0v = __ldcg((const float4*)&g_normpart[row][0]);
                        float4 n1v = __ldcg((const float4*)&g_normpart[row][4]);
                        float4 n2v = __ldcg((const float4*)&g_normpart[row][8]);
                        float4 n3v = __ldcg((const float4*)&g_normpart[row][12]);
                        float ss = ((n0v.x + n0v.y) + (n0v.z + n0v.w))
                                 + ((n1v.x + n1v.y) + (n1v.z + n1v.w))
                                 + ((n2v.x + n2v.y) + (n2v.z + n2v.w))
                                 + ((n3v.x + n3v.y) + (n3v.z + n3v.w));
                        const float rinv = __fdividef(1.0f, fmaxf(__fsqrt_rn(ss), 1e-12f));
                        const float4 p4 = __ldg((const float4*)&Pt[(size_t)row * XD + col0]);
                        float4 v = make_float4(acc[i][0] * rinv + p4.x, acc[i][1] * rinv + p4.y,
                                               acc[i][2] * rinv + p4.z, acc[i][3] * rinv + p4.w);
                        v = act4(v, id4, mx4);
                        __stcg((float4*)&g_h1[row * XD + col0], v);
                    }
                } else if (ph == 1) {
                    const int4   id4 = __ldg((const int4*)&idx_h2[col0]);
                    const float4 mx4 = __ldg((const float4*)&max_h2[col0]);
                    const float4 b4  = __ldg((const float4*)&bh2[col0]);
#pragma unroll
                    for (int i = 0; i < 2; i++) {
                        const int row = (ty << 1) + i;
                        float4 v = make_float4(acc[i][0] + b4.x, acc[i][1] + b4.y,
                                               acc[i][2] + b4.z, acc[i][3] + b4.w);
                        v = act4(v, id4, mx4);
                        __stcg((float4*)&g_h2[row * XD + col0], v);
                    }
                } else if (ph == 2) {
                    const int4   id4 = __ldg((const int4*)&idx_h3[col0]);
                    const float4 mx4 = __ldg((const float4*)&max_h3[col0]);
                    const float4 b4  = __ldg((const float4*)&bh3[col0]);
                    float* h3t = g_h3all + (size_t)s * BB * XD;
#pragma unroll
                    for (int i = 0; i < 2; i++) {
                        const int row = (ty << 1) + i;
                        float4 v = make_float4(acc[i][0] + b4.x, acc[i][1] + b4.y,
                                               acc[i][2] + b4.z, acc[i][3] + b4.w);
                        v = act4(v, id4, mx4);
                        __stcg((float4*)&h3t[row * XD + col0], v);
                    }
                } else {
                    const int4   id4 = __ldg((const int4*)&idx_rec[col0]);
                    const float4 mx4 = __ldg((const float4*)&max_rec[col0]);
                    const float4 b4  = __ldg((const float4*)&br[col0]);
#pragma unroll
                    for (int i = 0; i < 2; i++) {
                        const int row = (ty << 1) + i;
                        float4 v = make_float4(acc[i][0] + b4.x, acc[i][1] + b4.y,
                                               acc[i][2] + b4.z, acc[i][3] + b4.w);
                        v = act4(v, id4, mx4);
                        __stcg((float4*)&g_rs[row * XD + col0], v);
                        float sq = v.x * v.x + v.y * v.y + v.z * v.z + v.w * v.w;
                        sq += __shfl_xor_sync(0xffffffffu, sq, 1, 16);
                        sq += __shfl_xor_sync(0xffffffffu, sq, 2, 16);
                        sq += __shfl_xor_sync(0xffffffffu, sq, 4, 16);
                        sq += __shfl_xor_sync(0xffffffffu, sq, 8, 16);
                        if (tx == 0) __stcg(&g_normpart[row][nt], sq);
                    }
                }
                __syncthreads();
                if (tid == 0) red_release_add(&g_hcnt[slot * 8]);
            }
        }
    }
    gsync(mygen);

    // ================= Output GEMM: y = act(H3 @ Wo^T + bo) ================
    {
        float* pAs2 = smf; float* pBs = smf + 128 * P_ASTR;
        for (int task = bid; task < 512 * 4; task += NB) {
            const int t = task >> 2, ot = task & 3;
            float acc[2][4];
            gemm_task(g_h3all + (size_t)t * BB * XD, XD,
                      Wo + (size_t)(ot << 6) * XD, XD, 8, acc, pAs2, pBs, tx, ty);
            const int oc0 = (ot << 6) + (tx << 2);
            const int4   id4 = __ldg((const int4*)&idx_out[oc0]);
            const float4 mx4 = __ldg((const float4*)&max_out[oc0]);
            const float4 b4  = __ldg((const float4*)&bo[oc0]);
#pragma unroll
            for (int i = 0; i < 2; i++) {
                const int b = (ty << 1) + i;
                float4 v = make_float4(acc[i][0] + b4.x, acc[i][1] + b4.y,
                                       acc[i][2] + b4.z, acc[i][3] + b4.w);
                v = act4(v, id4, mx4);
                __stcg((float4*)&out[((size_t)b * TT + t) * OUTD + oc0], v);
            }
        }
    }
}

// ------------------------- launch ------------------------------------------
extern "C" void kernel_launch(void* const* d_in, const int* in_sizes, int n_in,
                              void* d_out, int out_size) {
    const float* x       = (const float*)d_in[0];
    const float* Wi      = (const float*)d_in[1];
    const float* bi      = (const float*)d_in[2];
    const float* Wh1     = (const float*)d_in[3];
    const float* bh1     = (const float*)d_in[4];
    const float* Wh2     = (const float*)d_in[5];
    const float* bh2     = (const float*)d_in[6];
    const float* Wh3     = (const float*)d_in[7];
    const float* bh3     = (const float*)d_in[8];
    const float* Wo      = (const float*)d_in[9];
    const float* bo      = (const float*)d_in[10];
    const float* Wr      = (const float*)d_in[11];
    const float* br      = (const float*)d_in[12];
    const float* max_in  = (const float*)d_in[13];
    const float* max_h1  = (const float*)d_in[14];
    const float* max_h2  = (const float*)d_in[15];
    const float* max_h3  = (const float*)d_in[16];
    const float* max_out = (const float*)d_in[17];
    const float* max_rec = (const float*)d_in[18];
    const int*   idx_in  = (const int*)d_in[19];
    const int*   idx_h1  = (const int*)d_in[20];
    const int*   idx_h2  = (const int*)d_in[21];
    const int*   idx_h3  = (const int*)d_in[22];
    const int*   idx_out = (const int*)d_in[23];
    const int*   idx_rec = (const int*)d_in[24];

    static int configured = 0;
    if (!configured) {
        cudaFuncSetAttribute(bnn_kernel, cudaFuncAttributeMaxDynamicSharedMemorySize,
                             SMEM_BYTES);
        configured = 1;
    }

    bnn_kernel<<<NB, NTH, SMEM_BYTES>>>(x, Wi, bi, Wh1, bh1, Wh2, bh2, Wh3, bh3,
                                        Wo, bo, Wr, br,
                                        max_in, max_h1, max_h2, max_h3, max_out, max_rec,
                                        idx_in, idx_h1, idx_h2, idx_h3, idx_out, idx_rec,
                                        (float*)d_out);
}

// round 17
// speedup vs baseline: 4.6008x; 1.2682x over previous
#include <cuda_runtime.h>
#include <cuda_bf16.h>
#include <stdint.h>
#include <math.h>

#define NB    128
#define NTH   512
#define BB    64
#define TT    512
#define IND   512
#define XD    1024
#define OUTD  256

// bf16 tiles: 64 rows x 128 cols, row stride 136 halves (272 B)
#define TILE_B   17408               // 64 * 136 * 2
#define SM_AHI   0
#define SM_ALO   TILE_B
#define SM_W     (2 * TILE_B)        // loop: 8 persistent tiles; pre: BHI/BLO scratch
#define SMEM_BYTES (10 * TILE_B)     // 174080

typedef unsigned long long ull;
typedef __nv_bfloat16 bf16;
typedef __nv_bfloat162 bf162;

// ------------------------- device scratch ---------------------------------
__device__ bf16 g_actinh[(size_t)BB * TT * XD];
__device__ bf16 g_actinl[(size_t)BB * TT * XD];
__device__ float g_P[(size_t)BB * TT * XD];        // bh1 folded in (fp32)
__device__ bf16 g_h3h[(size_t)TT * BB * XD];
__device__ bf16 g_h3l[(size_t)TT * BB * XD];
__device__ bf16 g_h1h[BB * XD];
__device__ bf16 g_h1l[BB * XD];
__device__ bf16 g_h2h[BB * XD];
__device__ bf16 g_h2l[BB * XD];
__device__ bf16 g_rsh[BB * XD];
__device__ bf16 g_rsl[BB * XD];
__device__ float g_normpart[BB][16];
__device__ float g_part[64 * 8 * 4096];
__device__ unsigned g_scnt[64 * 8];
__device__ unsigned g_hcnt[64 * 8];
__device__ unsigned g_barcnt;
__device__ unsigned g_bargen;

// ------------------------- scoped atomics ----------------------------------
__device__ __forceinline__ unsigned atom_acqrel_add(unsigned* p) {
    unsigned o;
    asm volatile("atom.acq_rel.gpu.add.u32 %0, [%1], %2;"
                 : "=r"(o) : "l"(p), "r"(1u) : "memory");
    return o;
}
__device__ __forceinline__ void red_release_add(unsigned* p) {
    asm volatile("red.release.gpu.add.u32 [%0], %1;" :: "l"(p), "r"(1u) : "memory");
}
__device__ __forceinline__ unsigned ld_acquire(const unsigned* p) {
    unsigned v;
    asm volatile("ld.acquire.gpu.u32 %0, [%1];" : "=r"(v) : "l"(p) : "memory");
    return v;
}

// ------------------------- mma.sync / ldmatrix wrappers --------------------
__device__ __forceinline__ uint32_t smem_u32(const void* p) {
    return (uint32_t)__cvta_generic_to_shared(p);
}
__device__ __forceinline__ void ldsm4(unsigned r[4], uint32_t addr) {
    asm volatile("ldmatrix.sync.aligned.m8n8.x4.shared.b16 {%0,%1,%2,%3}, [%4];"
        : "=r"(r[0]), "=r"(r[1]), "=r"(r[2]), "=r"(r[3]) : "r"(addr));
}
__device__ __forceinline__ void hmma(float c[4], const unsigned a[4],
                                     unsigned b0, unsigned b1) {
    asm volatile("mma.sync.aligned.m16n8k16.row.col.f32.bf16.bf16.f32 "
        "{%0,%1,%2,%3}, {%4,%5,%6,%7}, {%8,%9}, {%0,%1,%2,%3};"
        : "+f"(c[0]), "+f"(c[1]), "+f"(c[2]), "+f"(c[3])
        : "r"(a[0]), "r"(a[1]), "r"(a[2]), "r"(a[3]), "r"(b0), "r"(b1));
}

// 3-pass (AhiBhi + AhiBlo + AloBhi) 16x16-per-warp K=128 accumulate
__device__ __forceinline__ void hmma_frag(uint32_t aHiB, uint32_t aLoB,
                                          uint32_t bHiB, uint32_t bLoB,
                                          float c0[4], float c1[4]) {
#pragma unroll
    for (int ks = 0; ks < 8; ks++) {
        const uint32_t o = (uint32_t)(ks * 32);
        unsigned ah[4], al[4], bh[4], bl[4];
        ldsm4(ah, aHiB + o);
        ldsm4(al, aLoB + o);
        ldsm4(bh, bHiB + o);
        ldsm4(bl, bLoB + o);
        hmma(c0, ah, bh[0], bh[2]); hmma(c1, ah, bh[1], bh[3]);
        hmma(c0, ah, bl[0], bl[2]); hmma(c1, ah, bl[1], bl[3]);
        hmma(c0, al, bh[0], bh[2]); hmma(c1, al, bh[1], bh[3]);
    }
}

// ------------------------- branch-free fast activation ---------------------
__device__ __forceinline__ float rand_act(float v, int idx, float mx) {
    float en  = __expf(-v);
    float sig = __fdividef(1.0f, 1.0f + en);
    float th  = __fdividef(2.0f, 1.0f + en * en) - 1.0f;
    float sel = (v > 0.0f) ? 1.0507009873554805f * v
                           : 1.7580993408473766f * (__expf(v) - 1.0f);
    float r = (idx == 0) ? fmaxf(v, 0.0f)
            : (idx == 1) ? sig
            : (idx == 2) ? th
            : (idx == 3) ? ((v >= 0.0f) ? v : 0.1f * v)
            : sel;
    return fminf(r, mx);
}

// ------------------------- grid barrier (pre/post loop) --------------------
__device__ __forceinline__ void gsync(unsigned& mygen) {
    __threadfence();
    __syncthreads();
    if (threadIdx.x == 0) {
        unsigned old = atomicAdd(&g_barcnt, 1u);
        if (old == NB - 1u) {
            g_barcnt = 0u;
            __threadfence();
            atomicAdd(&g_bargen, 1u);
        } else {
            while (((volatile unsigned*)&g_bargen)[0] == mygen) { __nanosleep(64); }
        }
    }
    __syncthreads();
    mygen += 1u;
}

__device__ __forceinline__ void waitcnt(const unsigned* c0, const unsigned* c1, unsigned tgt) {
    if (threadIdx.x < 2) {
        const unsigned* p = threadIdx.x ? c1 : c0;
        while (ld_acquire(p) < tgt) {}
    }
    __syncthreads();
}

// ------------------------- staging ------------------------------------------
// fp32 -> bf16 hi/lo split (64 rows x 128 cols, row stride lds floats)
template<bool CONST>
__device__ __forceinline__ void stage_split(const float* src, int lds,
                                            char* hi, char* lo) {
    const int row = threadIdx.x >> 3;
    const int cb  = (threadIdx.x & 7) << 4;
    const float4* s = (const float4*)(src + (size_t)row * lds + cb);
    unsigned hp[8], lp[8];
#pragma unroll
    for (int j = 0; j < 4; j++) {
        float4 v = CONST ? __ldg(s + j) : __ldcg(s + j);
        bf162 h01 = __floats2bfloat162_rn(v.x, v.y);
        bf162 h23 = __floats2bfloat162_rn(v.z, v.w);
        float2 f01 = __bfloat1622float2(h01);
        float2 f23 = __bfloat1622float2(h23);
        bf162 l01 = __floats2bfloat162_rn(v.x - f01.x, v.y - f01.y);
        bf162 l23 = __floats2bfloat162_rn(v.z - f23.x, v.w - f23.y);
        hp[2 * j] = *(unsigned*)&h01; hp[2 * j + 1] = *(unsigned*)&h23;
        lp[2 * j] = *(unsigned*)&l01; lp[2 * j + 1] = *(unsigned*)&l23;
    }
    char* hd = hi + ((size_t)row * 136 + cb) * 2;
    char* ld = lo + ((size_t)row * 136 + cb) * 2;
    ((uint4*)hd)[0] = make_uint4(hp[0], hp[1], hp[2], hp[3]);
    ((uint4*)hd)[1] = make_uint4(hp[4], hp[5], hp[6], hp[7]);
    ((uint4*)ld)[0] = make_uint4(lp[0], lp[1], lp[2], lp[3]);
    ((uint4*)ld)[1] = make_uint4(lp[4], lp[5], lp[6], lp[7]);
}

// pre-split bf16 hi/lo global -> SMEM tiles (pure copy)
__device__ __forceinline__ void stage_copy(const bf16* sh, const bf16* sl, int lds,
                                           char* hi, char* lo) {
    const int row = threadIdx.x >> 3;
    const int cb  = (threadIdx.x & 7) << 4;
    const uint4* s0 = (const uint4*)(sh + (size_t)row * lds + cb);
    const uint4* s1 = (const uint4*)(sl + (size_t)row * lds + cb);
    uint4 a0 = __ldcg(s0), a1 = __ldcg(s0 + 1);
    uint4 b0 = __ldcg(s1), b1 = __ldcg(s1 + 1);
    uint4* hd = (uint4*)(hi + ((size_t)row * 136 + cb) * 2);
    uint4* ld = (uint4*)(lo + ((size_t)row * 136 + cb) * 2);
    hd[0] = a0; hd[1] = a1;
    ld[0] = b0; ld[1] = b1;
}

// split one fp32 pair into hi/lo bf16x2 words
__device__ __forceinline__ void split2(float v0, float v1, unsigned& h, unsigned& l) {
    bf162 hh = __floats2bfloat162_rn(v0, v1);
    float2 f = __bfloat1622float2(hh);
    bf162 ll = __floats2bfloat162_rn(v0 - f.x, v1 - f.y);
    h = *(unsigned*)&hh;
    l = *(unsigned*)&ll;
}

// ------------------------- main persistent kernel --------------------------
__global__ void __launch_bounds__(NTH, 1)
bnn_kernel(const float* __restrict__ x,
           const float* __restrict__ Wi,  const float* __restrict__ bi,
           const float* __restrict__ Wh1, const float* __restrict__ bh1,
           const float* __restrict__ Wh2, const float* __restrict__ bh2,
           const float* __restrict__ Wh3, const float* __restrict__ bh3,
           const float* __restrict__ Wo,  const float* __restrict__ bo,
           const float* __restrict__ Wr,  const float* __restrict__ br,
           const float* __restrict__ max_in,  const float* __restrict__ max_h1,
           const float* __restrict__ max_h2,  const float* __restrict__ max_h3,
           const float* __restrict__ max_out, const float* __restrict__ max_rec,
           const int* __restrict__ idx_in,  const int* __restrict__ idx_h1,
           const int* __restrict__ idx_h2,  const int* __restrict__ idx_h3,
           const int* __restrict__ idx_out, const int* __restrict__ idx_rec,
           float* __restrict__ out) {
    extern __shared__ char smraw[];

    const int bid = blockIdx.x;
    const int tid = threadIdx.x;
    const int tx  = tid & 15;
    const int ty  = tid >> 4;
    const int lane = tid & 31;
    const int w    = tid >> 5;         // warp 0..15
    const int mw   = w >> 2;           // 16-row block
    const int nw   = w & 3;            // 16-col block

    unsigned mygen = ((volatile unsigned*)&g_bargen)[0];

    // fragment addressing (row-major 136-stride bf16 tiles)
    const uint32_t fragoff = (uint32_t)(((lane & 15) * 136 + ((lane >> 4) << 3)) * 2);
    const uint32_t aHiB = smem_u32(smraw + SM_AHI) + (uint32_t)(mw * 16 * 272) + fragoff;
    const uint32_t aLoB = smem_u32(smraw + SM_ALO) + (uint32_t)(mw * 16 * 272) + fragoff;
    const uint32_t bPreHi = smem_u32(smraw + SM_W) + (uint32_t)(nw * 16 * 272) + fragoff;
    const uint32_t bPreLo = bPreHi + (uint32_t)TILE_B;

    // fragment epilogue coordinates
    const int fr0 = mw * 16 + (lane >> 2);         // rows fr0, fr0+8
    const int fc0 = nw * 16 + ((lane & 3) << 1);   // col pairs fc0, fc0+8

    // ---- init (every launch) ----
    for (int i = bid * NTH + tid; i < BB * XD / 2; i += NB * NTH) {
        ((unsigned*)g_rsh)[i] = 0u;
        ((unsigned*)g_rsl)[i] = 0u;
    }
    if (bid == 0) {
        for (int j = tid; j < BB * 16; j += NTH) ((float*)g_normpart)[j] = 0.0f;
        if (tid < 64 * 8) { g_scnt[tid] = 0u; g_hcnt[tid] = 0u; }
    }
    gsync(mygen);

    // ================= Phase A: actin = act(x @ Wi^T + bi) -> bf16 hi/lo ===
    for (int task = bid; task < 512 * 16; task += NB) {
        const int rt = task >> 4, nt2 = task & 15;
        float c0[4] = {0.f, 0.f, 0.f, 0.f}, c1[4] = {0.f, 0.f, 0.f, 0.f};
        for (int c = 0; c < 4; c++) {
            stage_split<false>(x + (size_t)rt * 64 * IND + c * 128, IND,
                               smraw + SM_AHI, smraw + SM_ALO);
            stage_split<true>(Wi + (size_t)(nt2 << 6) * IND + c * 128, IND,
                              smraw + SM_W, smraw + SM_W + TILE_B);
            __syncthreads();
            hmma_frag(aHiB, aLoB, bPreHi, bPreLo, c0, c1);
            __syncthreads();
        }
#pragma unroll
        for (int half = 0; half < 2; half++) {          // col pair fc0 / fc0+8
            const float* cc = half ? c1 : c0;
            const int gc = (nt2 << 6) + fc0 + 8 * half;
            const int2   id2 = __ldg((const int2*)&idx_in[gc]);
            const float2 mx2 = __ldg((const float2*)&max_in[gc]);
            const float2 b2  = __ldg((const float2*)&bi[gc]);
#pragma unroll
            for (int rr = 0; rr < 2; rr++) {            // row fr0 / fr0+8
                const int g = rt * 64 + fr0 + 8 * rr;
                const int b = g >> 9, t = g & 511;
                float v0 = rand_act(cc[2 * rr + 0] + b2.x, id2.x, mx2.x);
                float v1 = rand_act(cc[2 * rr + 1] + b2.y, id2.y, mx2.y);
                unsigned hh, ll;
                split2(v0, v1, hh, ll);
                const size_t off = (size_t)(t * BB + b) * XD + gc;
                __stcg((unsigned*)&g_actinh[off], hh);
                __stcg((unsigned*)&g_actinl[off], ll);
            }
        }
    }
    gsync(mygen);

    // ================= Phase B: P = actin @ Wh1a^T + bh1 (fp32) ============
    for (int task = bid; task < 512 * 16; task += NB) {
        const int rt = task >> 4, nt2 = task & 15;
        float c0[4] = {0.f, 0.f, 0.f, 0.f}, c1[4] = {0.f, 0.f, 0.f, 0.f};
        for (int c = 0; c < 8; c++) {
            stage_copy(g_actinh + (size_t)rt * 64 * XD + c * 128,
                       g_actinl + (size_t)rt * 64 * XD + c * 128, XD,
                       smraw + SM_AHI, smraw + SM_ALO);
            stage_split<true>(Wh1 + (size_t)(nt2 << 6) * (2 * XD) + c * 128, 2 * XD,
                              smraw + SM_W, smraw + SM_W + TILE_B);
            __syncthreads();
            hmma_frag(aHiB, aLoB, bPreHi, bPreLo, c0, c1);
            __syncthreads();
        }
#pragma unroll
        for (int half = 0; half < 2; half++) {
            const float* cc = half ? c1 : c0;
            const int gc = (nt2 << 6) + fc0 + 8 * half;
            const float2 b2 = __ldg((const float2*)&bh1[gc]);
#pragma unroll
            for (int rr = 0; rr < 2; rr++) {
                const int row = rt * 64 + fr0 + 8 * rr;
                __stcg((float2*)&g_P[(size_t)row * XD + gc],
                       make_float2(cc[2 * rr + 0] + b2.x, cc[2 * rr + 1] + b2.y));
            }
        }
    }
    gsync(mygen);

    // ================= loop setup: pre-split persistent weights ============
    const int nt = bid >> 3;
    const int sp = bid & 7;
    const int n0 = nt << 6;
    const int k0 = sp << 7;
    const int col0 = n0 + (tx << 2);

    {
        const float* wsrc[4] = { Wh1 + XD + (size_t)n0 * (2 * XD) + k0,
                                 Wh2 + (size_t)n0 * XD + k0,
                                 Wh3 + (size_t)n0 * XD + k0,
                                 Wr  + (size_t)n0 * XD + k0 };
        const int ldw[4] = { 2 * XD, XD, XD, XD };
#pragma unroll 1
        for (int ph = 0; ph < 4; ph++)
            stage_split<true>(wsrc[ph], ldw[ph],
                              smraw + SM_W + ph * (2 * TILE_B),
                              smraw + SM_W + ph * (2 * TILE_B) + TILE_B);
    }
    __syncthreads();

    // ================= time loop ============================================
    for (int s = 0; s < TT; s++) {
        const unsigned e = (unsigned)(s + 1);
#pragma unroll 1
        for (int ph = 0; ph < 4; ph++) {
            const int pslot = (ph == 0) ? 3 : (ph - 1);
            const unsigned tgt = (ph == 0) ? (unsigned)s : e;
            waitcnt(&g_hcnt[(pslot * 16 + 2 * sp) * 8],
                    &g_hcnt[(pslot * 16 + 2 * sp + 1) * 8], tgt);

            // ---- stage A: copy pre-split bf16 hi/lo slice ----
            if (ph == 0)      stage_copy(g_rsh + k0, g_rsl + k0, XD,
                                         smraw + SM_AHI, smraw + SM_ALO);
            else if (ph == 1) stage_copy(g_h1h + k0, g_h1l + k0, XD,
                                         smraw + SM_AHI, smraw + SM_ALO);
            else if (ph == 2) stage_copy(g_h2h + k0, g_h2l + k0, XD,
                                         smraw + SM_AHI, smraw + SM_ALO);
            else              stage_copy(g_h3h + (size_t)s * BB * XD + k0,
                                         g_h3l + (size_t)s * BB * XD + k0, XD,
                                         smraw + SM_AHI, smraw + SM_ALO);
            __syncthreads();

            // ---- 3-pass HMMA 16x16/warp vs persistent weight tile ----
            const uint32_t bHiB = smem_u32(smraw + SM_W + ph * (2 * TILE_B))
                                + (uint32_t)(nw * 16 * 272) + fragoff;
            float c0[4] = {0.f, 0.f, 0.f, 0.f}, c1[4] = {0.f, 0.f, 0.f, 0.f};
            hmma_frag(aHiB, aLoB, bHiB, bHiB + (uint32_t)TILE_B, c0, c1);
            __syncthreads();

            // ---- store slab ----
            const int slot = ph * 16 + nt;
            {
                float* slab = g_part + ((size_t)slot * 8 + sp) * 4096;
                const int r0 = mw * 16 + (lane >> 2);
                const int cl = nw * 16 + ((lane & 3) << 1);
                __stcg((float2*)&slab[r0 * 64 + cl],           make_float2(c0[0], c0[1]));
                __stcg((float2*)&slab[(r0 + 8) * 64 + cl],     make_float2(c0[2], c0[3]));
                __stcg((float2*)&slab[r0 * 64 + cl + 8],       make_float2(c1[0], c1[1]));
                __stcg((float2*)&slab[(r0 + 8) * 64 + cl + 8], make_float2(c1[2], c1[3]));
            }
            __syncthreads();

            // ---- arrival counter; 8th block reduces + epilogue ----
            __shared__ unsigned s_old;
            if (tid == 0) s_old = atom_acqrel_add(&g_scnt[slot * 8]);
            __syncthreads();
            if (s_old == 8u * e - 1u) {
                float acc[2][4];
#pragma unroll
                for (int i = 0; i < 2; i++)
#pragma unroll
                    for (int j = 0; j < 4; j++) acc[i][j] = 0.0f;
#pragma unroll
                for (int sl = 0; sl < 8; sl++) {
                    const float* os = &g_part[((size_t)slot * 8 + sl) * 4096];
#pragma unroll
                    for (int i = 0; i < 2; i++) {
                        float4 pv = __ldcg((const float4*)&os[((ty << 1) + i) * 64 + (tx << 2)]);
                        acc[i][0] += pv.x; acc[i][1] += pv.y;
                        acc[i][2] += pv.z; acc[i][3] += pv.w;
                    }
                }
                if (ph == 0) {
                    const int4   id4 = __ldg((const int4*)&idx_h1[col0]);
                    const float4 mx4 = __ldg((const float4*)&max_h1[col0]);
                    const float* Pt = g_P + (size_t)s * BB * XD;
#pragma unroll
                    for (int i = 0; i < 2; i++) {
                        const int row = (ty << 1) + i;
                        float4 n0v = __ldcg((const float4*)&g_normpart[row][0]);
                        float4 n1v = __ldcg((const float4*)&g_normpart[row][4]);
                        float4 n2v = __ldcg((const float4*)&g_normpart[row][8]);
                        float4 n3v = __ldcg((const float4*)&g_normpart[row][12]);
                        float ss = ((n0v.x + n0v.y) + (n0v.z + n0v.w))
                                 + ((n1v.x + n1v.y) + (n1v.z + n1v.w))
                                 + ((n2v.x + n2v.y) + (n2v.z + n2v.w))
                                 + ((n3v.x + n3v.y) + (n3v.z + n3v.w));
                        const float rinv = __fdividef(1.0f, fmaxf(__fsqrt_rn(ss), 1e-12f));
                        const float4 p4 = __ldg((const float4*)&Pt[(size_t)row * XD + col0]);
                        float v0 = rand_act(acc[i][0] * rinv + p4.x, id4.x, mx4.x);
                        float v1 = rand_act(acc[i][1] * rinv + p4.y, id4.y, mx4.y);
                        float v2 = rand_act(acc[i][2] * rinv + p4.z, id4.z, mx4.z);
                        float v3 = rand_act(acc[i][3] * rinv + p4.w, id4.w, mx4.w);
                        unsigned h0, l0, h1w, l1w;
                        split2(v0, v1, h0, l0);
                        split2(v2, v3, h1w, l1w);
                        const size_t off = (size_t)row * XD + col0;
                        __stcg((uint2*)&g_h1h[off], make_uint2(h0, h1w));
                        __stcg((uint2*)&g_h1l[off], make_uint2(l0, l1w));
                    }
                } else if (ph == 1) {
                    const int4   id4 = __ldg((const int4*)&idx_h2[col0]);
                    const float4 mx4 = __ldg((const float4*)&max_h2[col0]);
                    const float4 b4  = __ldg((const float4*)&bh2[col0]);
#pragma unroll
                    for (int i = 0; i < 2; i++) {
                        const int row = (ty << 1) + i;
                        float v0 = rand_act(acc[i][0] + b4.x, id4.x, mx4.x);
                        float v1 = rand_act(acc[i][1] + b4.y, id4.y, mx4.y);
                        float v2 = rand_act(acc[i][2] + b4.z, id4.z, mx4.z);
                        float v3 = rand_act(acc[i][3] + b4.w, id4.w, mx4.w);
                        unsigned h0, l0, h1w, l1w;
                        split2(v0, v1, h0, l0);
                        split2(v2, v3, h1w, l1w);
                        const size_t off = (size_t)row * XD + col0;
                        __stcg((uint2*)&g_h2h[off], make_uint2(h0, h1w));
                        __stcg((uint2*)&g_h2l[off], make_uint2(l0, l1w));
                    }
                } else if (ph == 2) {
                    const int4   id4 = __ldg((const int4*)&idx_h3[col0]);
                    const float4 mx4 = __ldg((const float4*)&max_h3[col0]);
                    const float4 b4  = __ldg((const float4*)&bh3[col0]);
#pragma unroll
                    for (int i = 0; i < 2; i++) {
                        const int row = (ty << 1) + i;
                        float v0 = rand_act(acc[i][0] + b4.x, id4.x, mx4.x);
                        float v1 = rand_act(acc[i][1] + b4.y, id4.y, mx4.y);
                        float v2 = rand_act(acc[i][2] + b4.z, id4.z, mx4.z);
                        float v3 = rand_act(acc[i][3] + b4.w, id4.w, mx4.w);
                        unsigned h0, l0, h1w, l1w;
                        split2(v0, v1, h0, l0);
                        split2(v2, v3, h1w, l1w);
                        const size_t off = ((size_t)s * BB + row) * XD + col0;
                        __stcg((uint2*)&g_h3h[off], make_uint2(h0, h1w));
                        __stcg((uint2*)&g_h3l[off], make_uint2(l0, l1w));
                    }
                } else {
                    const int4   id4 = __ldg((const int4*)&idx_rec[col0]);
                    const float4 mx4 = __ldg((const float4*)&max_rec[col0]);
                    const float4 b4  = __ldg((const float4*)&br[col0]);
#pragma unroll
                    for (int i = 0; i < 2; i++) {
                        const int row = (ty << 1) + i;
                        float v0 = rand_act(acc[i][0] + b4.x, id4.x, mx4.x);
                        float v1 = rand_act(acc[i][1] + b4.y, id4.y, mx4.y);
                        float v2 = rand_act(acc[i][2] + b4.z, id4.z, mx4.z);
                        float v3 = rand_act(acc[i][3] + b4.w, id4.w, mx4.w);
                        unsigned h0, l0, h1w, l1w;
                        split2(v0, v1, h0, l0);
                        split2(v2, v3, h1w, l1w);
                        const size_t off = (size_t)row * XD + col0;
                        __stcg((uint2*)&g_rsh[off], make_uint2(h0, h1w));
                        __stcg((uint2*)&g_rsl[off], make_uint2(l0, l1w));
                        float sq = v0 * v0 + v1 * v1 + v2 * v2 + v3 * v3;
                        sq += __shfl_xor_sync(0xffffffffu, sq, 1, 16);
                        sq += __shfl_xor_sync(0xffffffffu, sq, 2, 16);
                        sq += __shfl_xor_sync(0xffffffffu, sq, 4, 16);
                        sq += __shfl_xor_sync(0xffffffffu, sq, 8, 16);
                        if (tx == 0) __stcg(&g_normpart[row][nt], sq);
                    }
                }
                __syncthreads();
                if (tid == 0) red_release_add(&g_hcnt[slot * 8]);
            }
        }
    }
    gsync(mygen);

    // ================= Output GEMM: y = act(H3 @ Wo^T + bo) (HMMA) =========
    for (int task = bid; task < 512 * 4; task += NB) {
        const int t = task >> 2, ot = task & 3;
        float c0[4] = {0.f, 0.f, 0.f, 0.f}, c1[4] = {0.f, 0.f, 0.f, 0.f};
        for (int c = 0; c < 8; c++) {
            stage_copy(g_h3h + (size_t)t * BB * XD + c * 128,
                       g_h3l + (size_t)t * BB * XD + c * 128, XD,
                       smraw + SM_AHI, smraw + SM_ALO);
            stage_split<true>(Wo + (size_t)(ot << 6) * XD + c * 128, XD,
                              smraw + SM_W, smraw + SM_W + TILE_B);
            __syncthreads();
            hmma_frag(aHiB, aLoB, bPreHi, bPreLo, c0, c1);
            __syncthreads();
        }
#pragma unroll
        for (int half = 0; half < 2; half++) {
            const float* cc = half ? c1 : c0;
            const int oc = (ot << 6) + fc0 + 8 * half;
            const int2   id2 = __ldg((const int2*)&idx_out[oc]);
            const float2 mx2 = __ldg((const float2*)&max_out[oc]);
            const float2 b2  = __ldg((const float2*)&bo[oc]);
#pragma unroll
            for (int rr = 0; rr < 2; rr++) {
                const int b = fr0 + 8 * rr;      // batch row
                float v0 = rand_act(cc[2 * rr + 0] + b2.x, id2.x, mx2.x);
                float v1 = rand_act(cc[2 * rr + 1] + b2.y, id2.y, mx2.y);
                __stcg((float2*)&out[((size_t)b * TT + t) * OUTD + oc],
                       make_float2(v0, v1));
            }
        }
    }
}

// ------------------------- launch ------------------------------------------
extern "C" void kernel_launch(void* const* d_in, const int* in_sizes, int n_in,
                              void* d_out, int out_size) {
    const float* x       = (const float*)d_in[0];
    const float* Wi      = (const float*)d_in[1];
    const float* bi      = (const float*)d_in[2];
    const float* Wh1     = (const float*)d_in[3];
    const float* bh1     = (const float*)d_in[4];
    const float* Wh2     = (const float*)d_in[5];
    const float* bh2     = (const float*)d_in[6];
    const float* Wh3     = (const float*)d_in[7];
    const float* bh3     = (const float*)d_in[8];
    const float* Wo      = (const float*)d_in[9];
    const float* bo      = (const float*)d_in[10];
    const float* Wr      = (const float*)d_in[11];
    const float* br      = (const float*)d_in[12];
    const float* max_in  = (const float*)d_in[13];
    const float* max_h1  = (const float*)d_in[14];
    const float* max_h2  = (const float*)d_in[15];
    const float* max_h3  = (const float*)d_in[16];
    const float* max_out = (const float*)d_in[17];
    const float* max_rec = (const float*)d_in[18];
    const int*   idx_in  = (const int*)d_in[19];
    const int*   idx_h1  = (const int*)d_in[20];
    const int*   idx_h2  = (const int*)d_in[21];
    const int*   idx_h3  = (const int*)d_in[22];
    const int*   idx_out = (const int*)d_in[23];
    const int*   idx_rec = (const int*)d_in[24];

    static int configured = 0;
    if (!configured) {
        cudaFuncSetAttribute(bnn_kernel, cudaFuncAttributeMaxDynamicSharedMemorySize,
                             SMEM_BYTES);
        configured = 1;
    }

    bnn_kernel<<<NB, NTH, SMEM_BYTES>>>(x, Wi, bi, Wh1, bh1, Wh2, bh2, Wh3, bh3,
                                        Wo, bo, Wr, br,
                                        max_in, max_h1, max_h2, max_h3, max_out, max_rec,
                                        idx_in, idx_h1, idx_h2, idx_h3, idx_out, idx_rec,
                                        (float*)d_out);
}